// round 4
// baseline (speedup 1.0000x reference)
#include <cuda_runtime.h>

// Problem constants (fixed by the dataset)
#define NN 50000
#define EE 800000
#define ET (EE + NN)   // edges + self loops
#define CC 256         // hidden = out channels
#define F1 128         // input features
#define GG 64          // graphs

// ---------------- scratch (device globals; no allocation allowed) ----------
__device__ float g_H[(size_t)NN * CC];     // h = x @ W (reused both layers)
__device__ float g_X2[(size_t)NN * CC];    // layer-1 output / layer-2 input
__device__ float g_gout[GG * CC];          // graph_emb accumulator (device-local)
__device__ float g_asrc[NN];
__device__ float g_adst[NN];
__device__ int   g_off[NN + 1];
__device__ int   g_deg[NN];
__device__ int   g_cur[NN];
__device__ int   g_esrc[ET];

__device__ __forceinline__ int clampN(int v) {
    return v < 0 ? 0 : (v >= NN ? NN - 1 : v);
}

// ---------------- init: deg=1 (self loop), cur=0, zero graph accumulator ----
__global__ void init_kernel() {
    int i = blockIdx.x * blockDim.x + threadIdx.x;
    if (i < NN) { g_deg[i] = 1; g_cur[i] = 0; }
    if (i < GG * CC) g_gout[i] = 0.f;
}

// ---------------- CSR build: count ------------------------------------------
__global__ void count_kernel(const int* __restrict__ ei) {
    int i = blockIdx.x * blockDim.x + threadIdx.x;
    if (i < EE) {
        int d = clampN(ei[EE + i]);   // dst row (edge_index[1])
        atomicAdd(&g_deg[d], 1);
    }
}

// ---------------- CSR build: exclusive scan (single block) ------------------
__global__ void scan_kernel() {
    __shared__ int sums[1024];
    const int t = threadIdx.x;
    const int CH = (NN + 1023) / 1024;   // 49
    int beg = t * CH;
    int end = beg + CH; if (end > NN) end = NN;
    int s = 0;
    for (int i = beg; i < end; i++) s += g_deg[i];
    sums[t] = s;
    __syncthreads();
    for (int d = 1; d < 1024; d <<= 1) {
        int v = 0;
        if (t >= d) v = sums[t - d];
        __syncthreads();
        if (t >= d) sums[t] += v;
        __syncthreads();
    }
    int base = (t == 0) ? 0 : sums[t - 1];
    s = base;
    for (int i = beg; i < end; i++) { s += g_deg[i]; g_off[i + 1] = s; }
    if (t == 0) g_off[0] = 0;
}

// ---------------- CSR build: fill edge sources (incl. self loops) -----------
__global__ void fill_kernel(const int* __restrict__ ei) {
    int i = blockIdx.x * blockDim.x + threadIdx.x;
    if (i < EE) {
        int d = clampN(ei[EE + i]);
        int sv = clampN(ei[i]);
        int p = atomicAdd(&g_cur[d], 1);
        g_esrc[g_off[d] + p] = sv;
    } else if (i < EE + NN) {
        int n = i - EE;
        int p = atomicAdd(&g_cur[n], 1);
        g_esrc[g_off[n] + p] = n;
    }
}

// ---------------- SGEMM: C[M,256] = A[M,K] * B[K,256] into g_H --------------
// 128x128 tile, BK=16, 256 threads, 8x8 micro-tile (scalar FFMA).
__global__ __launch_bounds__(256) void sgemm_kernel(
    const float* __restrict__ Aext, int use_x2,
    const float* __restrict__ B, int M, int K)
{
    const float* A = use_x2 ? g_X2 : Aext;
    float* C = g_H;
    __shared__ float As[16][128];
    __shared__ float Bs[16][128];
    const int bm = blockIdx.x * 128;
    const int bn = blockIdx.y * 128;
    const int tid = threadIdx.x;
    const int tx = tid & 15, ty = tid >> 4;

    float acc[8][8];
#pragma unroll
    for (int i = 0; i < 8; i++)
#pragma unroll
        for (int j = 0; j < 8; j++) acc[i][j] = 0.f;

    const int arow0 = tid >> 2;         // 0..63
    const int acol  = (tid & 3) * 4;    // 0,4,8,12
    const int brow  = tid >> 5;         // 0..7
    const int bcol  = (tid & 31) * 4;   // 0..124

    for (int kt = 0; kt < K; kt += 16) {
#pragma unroll
        for (int r = 0; r < 2; r++) {
            int row = bm + arow0 + r * 64;
            float4 v = make_float4(0.f, 0.f, 0.f, 0.f);
            if (row < M) v = *(const float4*)(A + (size_t)row * K + kt + acol);
            As[acol + 0][arow0 + r * 64] = v.x;
            As[acol + 1][arow0 + r * 64] = v.y;
            As[acol + 2][arow0 + r * 64] = v.z;
            As[acol + 3][arow0 + r * 64] = v.w;
        }
#pragma unroll
        for (int r = 0; r < 2; r++) {
            int row = kt + brow + r * 8;
            *(float4*)&Bs[brow + r * 8][bcol] =
                *(const float4*)(B + (size_t)row * CC + bn + bcol);
        }
        __syncthreads();
#pragma unroll
        for (int kk = 0; kk < 16; kk++) {
            float av[8], bv[8];
            float4 a0 = *(const float4*)&As[kk][ty * 8];
            float4 a1 = *(const float4*)&As[kk][ty * 8 + 4];
            float4 b0 = *(const float4*)&Bs[kk][tx * 8];
            float4 b1 = *(const float4*)&Bs[kk][tx * 8 + 4];
            av[0] = a0.x; av[1] = a0.y; av[2] = a0.z; av[3] = a0.w;
            av[4] = a1.x; av[5] = a1.y; av[6] = a1.z; av[7] = a1.w;
            bv[0] = b0.x; bv[1] = b0.y; bv[2] = b0.z; bv[3] = b0.w;
            bv[4] = b1.x; bv[5] = b1.y; bv[6] = b1.z; bv[7] = b1.w;
#pragma unroll
            for (int i = 0; i < 8; i++)
#pragma unroll
                for (int j = 0; j < 8; j++)
                    acc[i][j] = fmaf(av[i], bv[j], acc[i][j]);
        }
        __syncthreads();
    }
#pragma unroll
    for (int i = 0; i < 8; i++) {
        int row = bm + ty * 8 + i;
        if (row < M) {
            float* cp = C + (size_t)row * CC + bn + tx * 8;
            *(float4*)cp       = make_float4(acc[i][0], acc[i][1], acc[i][2], acc[i][3]);
            *(float4*)(cp + 4) = make_float4(acc[i][4], acc[i][5], acc[i][6], acc[i][7]);
        }
    }
}

// ---------------- per-node attention logit projections -----------------------
__global__ void alpha_kernel(const float* __restrict__ aw_s,
                             const float* __restrict__ aw_d) {
    int w = (blockIdx.x * blockDim.x + threadIdx.x) >> 5;
    if (w >= NN) return;
    int lane = threadIdx.x & 31;
    const float4* hr = (const float4*)(g_H + (size_t)w * CC);
    float s = 0.f, d = 0.f;
#pragma unroll
    for (int j = 0; j < 2; j++) {
        float4 h  = hr[lane * 2 + j];
        float4 a  = ((const float4*)aw_s)[lane * 2 + j];
        float4 dd = ((const float4*)aw_d)[lane * 2 + j];
        s += h.x * a.x + h.y * a.y + h.z * a.z + h.w * a.w;
        d += h.x * dd.x + h.y * dd.y + h.z * dd.z + h.w * dd.w;
    }
#pragma unroll
    for (int o = 16; o > 0; o >>= 1) {
        s += __shfl_xor_sync(0xFFFFFFFFu, s, o);
        d += __shfl_xor_sync(0xFFFFFFFFu, d, o);
    }
    if (lane == 0) { g_asrc[w] = s; g_adst[w] = d; }
}

// ---------------- per-dst-node online-softmax aggregation -------------------
// One warp per destination node: lane handles 8 contiguous channels.
template <bool ACT, bool GRAPH>
__global__ void aggregate_kernel(const float* __restrict__ bias,
                                 float* __restrict__ out_ext,
                                 const int* __restrict__ batch) {
    int w = (blockIdx.x * blockDim.x + threadIdx.x) >> 5;
    if (w >= NN) return;
    int lane = threadIdx.x & 31;
    int beg = g_off[w], end = g_off[w + 1];
    float ad = g_adst[w];
    float m = -1e30f, s = 0.f;
    float a0 = 0.f, a1 = 0.f, a2 = 0.f, a3 = 0.f;
    float a4 = 0.f, a5 = 0.f, a6 = 0.f, a7 = 0.f;
    const float4* H4 = (const float4*)g_H;
    for (int i = beg; i < end; i++) {
        int src = g_esrc[i];
        float e = g_asrc[src] + ad;
        e = e > 0.f ? e : 0.2f * e;                 // attention leaky relu
        float mn = fmaxf(m, e);
        float sc = __expf(m - mn);
        float p  = __expf(e - mn);
        s = s * sc + p;
        float4 v0 = H4[(size_t)src * 64 + lane * 2];
        float4 v1 = H4[(size_t)src * 64 + lane * 2 + 1];
        a0 = a0 * sc + p * v0.x;  a1 = a1 * sc + p * v0.y;
        a2 = a2 * sc + p * v0.z;  a3 = a3 * sc + p * v0.w;
        a4 = a4 * sc + p * v1.x;  a5 = a5 * sc + p * v1.y;
        a6 = a6 * sc + p * v1.z;  a7 = a7 * sc + p * v1.w;
        m = mn;
    }
    float inv = 1.f / s;
    int c = lane * 8;
    float o[8];
    o[0] = a0 * inv + bias[c + 0];  o[1] = a1 * inv + bias[c + 1];
    o[2] = a2 * inv + bias[c + 2];  o[3] = a3 * inv + bias[c + 3];
    o[4] = a4 * inv + bias[c + 4];  o[5] = a5 * inv + bias[c + 5];
    o[6] = a6 * inv + bias[c + 6];  o[7] = a7 * inv + bias[c + 7];
    if (ACT) {
#pragma unroll
        for (int j = 0; j < 8; j++) o[j] = o[j] > 0.f ? o[j] : 0.01f * o[j];
    }
    float* out = GRAPH ? out_ext : g_X2;
    float* op = out + (size_t)w * CC + c;
    *(float4*)op       = make_float4(o[0], o[1], o[2], o[3]);
    *(float4*)(op + 4) = make_float4(o[4], o[5], o[6], o[7]);
    if (GRAPH) {
        int g = batch[w];
        g = g < 0 ? 0 : (g >= GG ? GG - 1 : g);
        float* gp = g_gout + g * CC + c;   // device-local accumulator
#pragma unroll
        for (int j = 0; j < 8; j++) atomicAdd(gp + j, o[j]);
    }
}

// ---------------- copy graph accumulator into d_out (plain stores) ----------
__global__ void copy_gout_kernel(float* __restrict__ out) {
    int i = blockIdx.x * blockDim.x + threadIdx.x;
    if (i < GG * CC) out[(size_t)NN * CC + i] = g_gout[i];
}

// ---------------- launch -----------------------------------------------------
extern "C" void kernel_launch(void* const* d_in, const int* in_sizes, int n_in,
                              void* d_out, int out_size) {
    const float* x     = (const float*)d_in[0];
    const int*   ei    = (const int*)d_in[1];     // edge_index: int32 (JAX x64 off)
    const int*   batch = (const int*)d_in[2];     // batch: int32
    const float* W1    = (const float*)d_in[3];
    const float* as1   = (const float*)d_in[4];
    const float* ad1   = (const float*)d_in[5];
    const float* b1    = (const float*)d_in[6];
    const float* W2    = (const float*)d_in[7];
    const float* as2   = (const float*)d_in[8];
    const float* ad2   = (const float*)d_in[9];
    const float* b2    = (const float*)d_in[10];

    float* out = (float*)d_out;

    const int T = 256;
    // CSR build (dst is identical for both layers; built once per launch)
    init_kernel<<<(NN + T - 1) / T, T>>>();
    count_kernel<<<(EE + T - 1) / T, T>>>(ei);
    scan_kernel<<<1, 1024>>>();
    fill_kernel<<<(EE + NN + T - 1) / T, T>>>(ei);

    dim3 ggrid((NN + 127) / 128, CC / 128);
    const int WGRID = (NN * 32 + T - 1) / T;

    // Layer 1
    sgemm_kernel<<<ggrid, T>>>(x, 0, W1, NN, F1);
    alpha_kernel<<<WGRID, T>>>(as1, ad1);
    aggregate_kernel<true, false><<<WGRID, T>>>(b1, nullptr, nullptr);

    // Layer 2
    sgemm_kernel<<<ggrid, T>>>(nullptr, 1, W2, NN, CC);
    alpha_kernel<<<WGRID, T>>>(as2, ad2);
    aggregate_kernel<false, true><<<WGRID, T>>>(b2, out, batch);

    copy_gout_kernel<<<(GG * CC + T - 1) / T, T>>>(out);
}